// round 12
// baseline (speedup 1.0000x reference)
#include <cuda_runtime.h>

#define TOTAL_OPS 102400
#define ND 1024
#define NW 64
#define E 256
#define H1N 32
#define H2N 16
#define XPAD 20                      // floats per row in x staging buffer
#define ROWS_PB 512
#define THR 256
#define MAXDAG 12

// ---------------- device scratch (no allocations allowed) ----------------
__device__ unsigned g_maxbits;
__device__ float    g_sum;
__device__ unsigned g_cnt1;
__device__ unsigned g_cnt2;

typedef unsigned long long ull;

// ---------------- packed fp32x2 helpers (sm_103a FFMA2 path) ----------------
__device__ __forceinline__ ull fma2(ull a, ull b, ull c) {
    ull d;
    asm("fma.rn.f32x2 %0, %1, %2, %3;" : "=l"(d) : "l"(a), "l"(b), "l"(c));
    return d;
}
__device__ __forceinline__ ull splat2(float x) {
    ull d;
    asm("mov.b64 %0, {%1, %1};" : "=l"(d) : "f"(x));
    return d;
}
__device__ __forceinline__ void unpack2(ull v, float& lo, float& hi) {
    asm("mov.b64 {%0, %1}, %2;" : "=f"(lo), "=f"(hi) : "l"(v));
}

__device__ __forceinline__ unsigned encf(float f) {
    unsigned b = __float_as_uint(f);
    return (b & 0x80000000u) ? ~b : (b | 0x80000000u);
}
__device__ __forceinline__ float decf(unsigned u) {
    return (u & 0x80000000u) ? __uint_as_float(u & 0x7FFFFFFFu)
                             : __uint_as_float(~u);
}

// ---------------- K1: prlvl branch, 8 dags/block, fully self-contained -------
// Inline-computes yW (y@W1y) for its 8 dags and zc (b1+z@W1z). Block 0 also
// resets the k_ops softmax scalars (stream order: completes before k_ops).
__global__ void __launch_bounds__(512) k_prlvl(
    const float* __restrict__ prW1, const float* __restrict__ prb1,
    const float* __restrict__ prW2, const float* __restrict__ prb2,
    const float* __restrict__ prW3, const float* __restrict__ prb3,
    const float* __restrict__ msk, const float* __restrict__ y,
    const float* __restrict__ z,
    float* __restrict__ out, int nops)
{
    __shared__ __align__(16) float sW2[H1N * H2N];
    __shared__ float sb2[H2N], sW3[H2N];
    __shared__ float sb3;
    __shared__ float sw1[H1N], szc[H1N];
    __shared__ float sbase[8][H1N];
    __shared__ float part[8][2][H1N];
    __shared__ float partz[8][H1N];
    __shared__ float redm[8][2], reds[8][2];

    int t = threadIdx.x;
    int g = t >> 6;                      // dag group 0..7
    int w = t & 63;                      // worker 0..63
    int d = blockIdx.x * 8 + g;

    if (blockIdx.x == 0 && t == 0) {
        g_maxbits = 0u; g_sum = 0.f; g_cnt1 = 0u; g_cnt2 = 0u;
    }

    if (t < H1N * H2N) sW2[t] = prW2[t];
    if (t < H2N) { sb2[t] = prb2[t]; sW3[t] = prW3[t]; }
    if (t == 0) sb3 = prb3[0];
    if (t < H1N) sw1[t] = prW1[t];       // limit row of W1

    // --- inline yW for 8 dags: thread = (dd, half, j); 128-k chains ---
    {
        int dd = t >> 6, half = (t >> 5) & 1, j = t & 31;
        int dg = blockIdx.x * 8 + dd;
        const float* yp = &y[(size_t)dg * E + half * 128];
        const float* Wp = prW1 + (size_t)(1 + half * 128) * H1N + j;
        float c = 0.f;
#pragma unroll 16
        for (int kk = 0; kk < 128; kk++) c += yp[kk] * Wp[kk * H1N];
        part[dd][half][j] = c;
    }
    // --- inline zc: threads 0-255: (q, j), 32-k chains ---
    if (t < 256) {
        int q = t >> 5, j = t & 31;
        const float* zp = z + q * 32;
        const float* Wp = prW1 + (size_t)(E + 1 + q * 32) * H1N + j;
        float c = 0.f;
#pragma unroll 8
        for (int kk = 0; kk < 32; kk++) c += zp[kk] * Wp[kk * H1N];
        partz[q][j] = c;
    }
    __syncthreads();
    if (t < 8 * H1N) {                   // combine yW halves
        int dd = t >> 5, j = t & 31;
        sbase[dd][j] = part[dd][0][j] + part[dd][1][j];
    }
    if (t < H1N) {
        float c = prb1[t];
#pragma unroll
        for (int q = 0; q < 8; q++) c += partz[q][t];
        szc[t] = c;
    }
    __syncthreads();

    float limit = (float)(w + 1);
    const float* base = sbase[g];
    float h2[H2N];
#pragma unroll
    for (int j2 = 0; j2 < H2N; j2++) h2[j2] = sb2[j2];
#pragma unroll
    for (int j = 0; j < H1N; j++) {
        float v = fmaxf(base[j] + szc[j] + limit * sw1[j], 0.f);
        const float4* w2 = (const float4*)&sW2[j * H2N];
#pragma unroll
        for (int q2 = 0; q2 < 4; q2++) {
            float4 wv = w2[q2];
            h2[4 * q2 + 0] += v * wv.x;
            h2[4 * q2 + 1] += v * wv.y;
            h2[4 * q2 + 2] += v * wv.z;
            h2[4 * q2 + 3] += v * wv.w;
        }
    }
    float logit = sb3;
#pragma unroll
    for (int j2 = 0; j2 < H2N; j2++) logit += fmaxf(h2[j2], 0.f) * sW3[j2];
    logit -= (1.f - msk[d * NW + w]) * 1000.f;

    float m = logit;
#pragma unroll
    for (int o = 16; o > 0; o >>= 1) m = fmaxf(m, __shfl_xor_sync(0xffffffffu, m, o));
    if ((w & 31) == 0) redm[g][w >> 5] = m;
    __syncthreads();
    m = fmaxf(redm[g][0], redm[g][1]);
    float e = expf(logit - m);
    float s = e;
#pragma unroll
    for (int o = 16; o > 0; o >>= 1) s += __shfl_xor_sync(0xffffffffu, s, o);
    if ((w & 31) == 0) reds[g][w >> 5] = s;
    __syncthreads();
    s = reds[g][0] + reds[g][1];
    out[nops + d * NW + w] = e / s;
}

// ---------------- K2: op MLP + inline yW + fused global softmax --------------
// 256 thr, 512 rows/block, 200 blocks (all resident at 2 CTA/SM).
// Mainloop: x staged via SMEM (coalesced LDG->STS->LDS.128) in 16-k chunks;
// 4 rows x 16 cols register tile, weights via broadcast LDS.128.
// Per-block inline: num_ops scan, zc, and yW for this tile's <=12 dags.
__global__ void __launch_bounds__(THR, 2) k_ops(
    const float* __restrict__ x, const float* __restrict__ opW1,
    const float* __restrict__ opb1,
    const float* __restrict__ opW2, const float* __restrict__ opb2,
    const float* __restrict__ opW3, const float* __restrict__ opb3,
    const float* __restrict__ op_msk, const int* __restrict__ num_ops,
    const float* __restrict__ y, const float* __restrict__ z,
    float* __restrict__ out, int nrows)
{
    extern __shared__ float dynS[];
    float* sW = dynS;                        // 8192 floats: W1 x-part [k][32]
    float* sX = dynS + 8192;                 // 512*XPAD floats
    // after mainloop, dynS[0 .. 512*33) reused as h1 stage

    __shared__ int sCum[ND];
    __shared__ __align__(16) float sW2[H1N * H2N];
    __shared__ float sb2[H2N], sW3[H2N], szc[H1N];
    __shared__ float sb3;
    __shared__ float sYW[MAXDAG][H1N];
    __shared__ float part[8][H1N];
    __shared__ float wred[8];
    __shared__ int wsum[8];
    __shared__ float sBcast;
    __shared__ int sDlo;

    int t = threadIdx.x;
    int w = t >> 5, l = t & 31;
    int row0 = blockIdx.x * ROWS_PB;

    // --- stage W1 x-part [k][32] + small weights ---
    {
        const float4* gW4 = (const float4*)opW1;
        float4* sW4 = (float4*)sW;
#pragma unroll
        for (int i = 0; i < 8; i++) sW4[i * THR + t] = gW4[i * THR + t];
    }
    for (int i = t; i < H1N * H2N; i += THR) sW2[i] = opW2[i];
    if (t < H2N) { sb2[t] = opb2[t]; sW3[t] = opW3[t]; }
    if (t == 0) sb3 = opb3[0];

    // --- inline inclusive scan of num_ops (1024) into sCum ---
    {
        int vloc[4]; int tsum = 0;
#pragma unroll
        for (int i = 0; i < 4; i++) { vloc[i] = num_ops[t * 4 + i]; tsum += vloc[i]; }
        int sc = tsum;
#pragma unroll
        for (int o = 1; o < 32; o <<= 1) {
            int nv = __shfl_up_sync(0xffffffffu, sc, o);
            if (l >= o) sc += nv;
        }
        if (l == 31) wsum[w] = sc;
        __syncthreads();
        int woff = 0;
#pragma unroll
        for (int q = 0; q < 8; q++) if (q < w) woff += wsum[q];
        int run = woff + sc - tsum;
#pragma unroll
        for (int i = 0; i < 4; i++) { run += vloc[i]; sCum[t * 4 + i] = run; }
    }

    // --- inline zc: (q = t>>5, j = t&31), 32-k chains over W1z ---
    {
        int q = w, j = l;
        const float* zp = z + q * 32;
        const float* Wp = opW1 + (size_t)(2 * E + q * 32) * H1N + j;
        float c = 0.f;
#pragma unroll 8
        for (int kk = 0; kk < 32; kk++) c += zp[kk] * Wp[kk * H1N];
        part[q][j] = c;
    }
    __syncthreads();
    if (t < H1N) {
        float c = opb1[t];
#pragma unroll
        for (int q = 0; q < 8; q++) c += part[q][t];
        szc[t] = c;
    }
    // --- dag range of this tile ---
    if (t == 0) {
        int i0 = row0;
        int dlo = 0;
#pragma unroll
        for (int s = 512; s > 0; s >>= 1)
            if (dlo + s <= ND - 1 && sCum[dlo + s - 1] <= i0) dlo += s;
        sDlo = dlo;
    }
    __syncthreads();
    int dlo = sDlo;
    // --- inline yW for tile dags [dlo, dlo+MAXDAG): (q, j) 32-k chains ---
    {
        int iN = min(row0 + ROWS_PB - 1, nrows - 1);
        for (int dd = 0; dd < MAXDAG; dd++) {
            int d = dlo + dd;
            if (d >= ND) break;
            int dstart = (d == 0) ? 0 : sCum[d - 1];
            if (dstart > iN) break;          // no rows of this dag in tile
            int q = w, j = l;
            const float* yp = &y[(size_t)d * E + q * 32];
            const float* Wp = opW1 + (size_t)(E + q * 32) * H1N + j;
            float c = 0.f;
#pragma unroll 8
            for (int kk = 0; kk < 32; kk++) c += yp[kk] * Wp[kk * H1N];
            part[q][j] = c;
            __syncthreads();
            if (t < H1N) {
                float cc = szc[t];
#pragma unroll
                for (int qq = 0; qq < 8; qq++) cc += part[qq][t];
                sYW[dd][t] = cc;             // zc folded in
            }
            __syncthreads();
        }
    }

    // --- main GEMM: 16 chunks of 16 k; coalesced staging ---
    int colhalf = t >> 7;               // 0: cols 0-15, 1: cols 16-31
    int rt = t & 127;                   // row-thread 0..127

    int sr[8], sc4[8];
#pragma unroll
    for (int i = 0; i < 8; i++) {
        int idx = i * THR + t;
        sr[i] = idx >> 2;               // row 0..511
        sc4[i] = idx & 3;               // float4 within 16-k chunk
    }

    ull a0[8], a1[8], a2[8], a3[8];
#pragma unroll
    for (int q = 0; q < 8; q++) { a0[q] = 0ull; a1[q] = 0ull; a2[q] = 0ull; a3[q] = 0ull; }
    const ulonglong2* sWu = (const ulonglong2*)sW;

    float4 pf[8];
#pragma unroll
    for (int i = 0; i < 8; i++) {
        int row = min(row0 + sr[i], nrows - 1);
        pf[i] = *(const float4*)&x[(size_t)row * E + sc4[i] * 4];
    }

    for (int ch = 0; ch < 16; ch++) {
        __syncthreads();                 // previous chunk fully consumed
#pragma unroll
        for (int i = 0; i < 8; i++)
            *(float4*)&sX[sr[i] * XPAD + sc4[i] * 4] = pf[i];
        if (ch < 15) {
#pragma unroll
            for (int i = 0; i < 8; i++) {
                int row = min(row0 + sr[i], nrows - 1);
                pf[i] = *(const float4*)&x[(size_t)row * E + (ch + 1) * 16 + sc4[i] * 4];
            }
        }
        __syncthreads();                 // chunk ch visible
#pragma unroll
        for (int k4 = 0; k4 < 4; k4++) {
            float4 v0 = *(const float4*)&sX[(rt      ) * XPAD + k4 * 4];
            float4 v1 = *(const float4*)&sX[(rt + 128) * XPAD + k4 * 4];
            float4 v2 = *(const float4*)&sX[(rt + 256) * XPAD + k4 * 4];
            float4 v3 = *(const float4*)&sX[(rt + 384) * XPAD + k4 * 4];
            float f0[4] = {v0.x, v0.y, v0.z, v0.w};
            float f1[4] = {v1.x, v1.y, v1.z, v1.w};
            float f2[4] = {v2.x, v2.y, v2.z, v2.w};
            float f3[4] = {v3.x, v3.y, v3.z, v3.w};
#pragma unroll
            for (int kk = 0; kk < 4; kk++) {
                int k = ch * 16 + k4 * 4 + kk;
                ull s0 = splat2(f0[kk]);
                ull s1 = splat2(f1[kk]);
                ull s2 = splat2(f2[kk]);
                ull s3 = splat2(f3[kk]);
                const ulonglong2* wp = &sWu[k * 8 + colhalf * 4];
                ulonglong2 w0 = wp[0], w1 = wp[1], w2 = wp[2], w3 = wp[3];
                a0[0] = fma2(s0, w0.x, a0[0]); a0[1] = fma2(s0, w0.y, a0[1]);
                a0[2] = fma2(s0, w1.x, a0[2]); a0[3] = fma2(s0, w1.y, a0[3]);
                a0[4] = fma2(s0, w2.x, a0[4]); a0[5] = fma2(s0, w2.y, a0[5]);
                a0[6] = fma2(s0, w3.x, a0[6]); a0[7] = fma2(s0, w3.y, a0[7]);
                a1[0] = fma2(s1, w0.x, a1[0]); a1[1] = fma2(s1, w0.y, a1[1]);
                a1[2] = fma2(s1, w1.x, a1[2]); a1[3] = fma2(s1, w1.y, a1[3]);
                a1[4] = fma2(s1, w2.x, a1[4]); a1[5] = fma2(s1, w2.y, a1[5]);
                a1[6] = fma2(s1, w3.x, a1[6]); a1[7] = fma2(s1, w3.y, a1[7]);
                a2[0] = fma2(s2, w0.x, a2[0]); a2[1] = fma2(s2, w0.y, a2[1]);
                a2[2] = fma2(s2, w1.x, a2[2]); a2[3] = fma2(s2, w1.y, a2[3]);
                a2[4] = fma2(s2, w2.x, a2[4]); a2[5] = fma2(s2, w2.y, a2[5]);
                a2[6] = fma2(s2, w3.x, a2[6]); a2[7] = fma2(s2, w3.y, a2[7]);
                a3[0] = fma2(s3, w0.x, a3[0]); a3[1] = fma2(s3, w0.y, a3[1]);
                a3[2] = fma2(s3, w1.x, a3[2]); a3[3] = fma2(s3, w1.y, a3[3]);
                a3[4] = fma2(s3, w2.x, a3[4]); a3[5] = fma2(s3, w2.y, a3[5]);
                a3[6] = fma2(s3, w3.x, a3[6]); a3[7] = fma2(s3, w3.y, a3[7]);
            }
        }
    }

    // --- stage h1 to dynS (stride-33), reuse weight + x region ---
    __syncthreads();
    float* hst = dynS;
    {
        float* d0 = &hst[(rt      ) * 33 + colhalf * 16];
        float* d1 = &hst[(rt + 128) * 33 + colhalf * 16];
        float* d2 = &hst[(rt + 256) * 33 + colhalf * 16];
        float* d3 = &hst[(rt + 384) * 33 + colhalf * 16];
#pragma unroll
        for (int q = 0; q < 8; q++) {
            unpack2(a0[q], d0[2 * q], d0[2 * q + 1]);
            unpack2(a1[q], d1[2 * q], d1[2 * q + 1]);
            unpack2(a2[q], d2[2 * q], d2[2 * q + 1]);
            unpack2(a3[q], d3[2 * q], d3[2 * q + 1]);
        }
    }
    __syncthreads();

    // --- epilogue: 2 rows per thread, logits stay in registers ---
    float lg[2];
    float m = -3.402823466e38f;
#pragma unroll
    for (int r = 0; r < 2; r++) {
        int lr = t + r * THR;
        int i = row0 + lr;
        lg[r] = -3.402823466e38f;
        if (i < nrows) {
            int d = 0;
#pragma unroll
            for (int s = 512; s > 0; s >>= 1)
                if (d + s <= ND - 1 && sCum[d + s - 1] <= i) d += s;
            const float* hs = &hst[lr * 33];
            float bwv[H1N];
            int dd = d - dlo;
            if (dd < MAXDAG) {
#pragma unroll
                for (int j = 0; j < H1N; j++) bwv[j] = sYW[dd][j];
            } else {
                // correctness fallback (never triggered for uniform num_ops)
#pragma unroll
                for (int j = 0; j < H1N; j++) bwv[j] = szc[j];
                for (int k = 0; k < E; k++) {
                    float yv = y[(size_t)d * E + k];
                    const float* Wp = opW1 + (size_t)(E + k) * H1N;
#pragma unroll
                    for (int j = 0; j < H1N; j++) bwv[j] += yv * Wp[j];
                }
            }
            float h2[H2N];
#pragma unroll
            for (int j2 = 0; j2 < H2N; j2++) h2[j2] = sb2[j2];
#pragma unroll
            for (int j = 0; j < H1N; j++) {
                float v = fmaxf(hs[j] + bwv[j], 0.f);
                const float4* w2 = (const float4*)&sW2[j * H2N];
#pragma unroll
                for (int q2 = 0; q2 < 4; q2++) {
                    float4 wv = w2[q2];
                    h2[4 * q2 + 0] += v * wv.x;
                    h2[4 * q2 + 1] += v * wv.y;
                    h2[4 * q2 + 2] += v * wv.z;
                    h2[4 * q2 + 3] += v * wv.w;
                }
            }
            float logit = sb3;
#pragma unroll
            for (int j2 = 0; j2 < H2N; j2++) logit += fmaxf(h2[j2], 0.f) * sW3[j2];
            logit -= (1.f - op_msk[i]) * 1000.f;
            lg[r] = logit;
            m = fmaxf(m, logit);
        }
    }

#pragma unroll
    for (int o = 16; o > 0; o >>= 1) m = fmaxf(m, __shfl_xor_sync(0xffffffffu, m, o));
    if (l == 0) wred[w] = m;
    __syncthreads();

    // --- grid barrier 1: global max ---
    if (t == 0) {
        float bm = wred[0];
#pragma unroll
        for (int q = 1; q < 8; q++) bm = fmaxf(bm, wred[q]);
        atomicMax(&g_maxbits, encf(bm));
        __threadfence();
        atomicAdd(&g_cnt1, 1u);
        volatile unsigned* vc = &g_cnt1;
        while (*vc < gridDim.x) { }
        __threadfence();
        sBcast = decf(*(volatile unsigned*)&g_maxbits);
    }
    __syncthreads();
    float gm = sBcast;

    float e0 = (lg[0] > -1e38f) ? expf(lg[0] - gm) : 0.f;
    float e1 = (lg[1] > -1e38f) ? expf(lg[1] - gm) : 0.f;
    float s = e0 + e1;
#pragma unroll
    for (int o = 16; o > 0; o >>= 1) s += __shfl_xor_sync(0xffffffffu, s, o);
    if (l == 0) wred[w] = s;
    __syncthreads();

    // --- grid barrier 2: global sum ---
    if (t == 0) {
        float bs = 0.f;
#pragma unroll
        for (int q = 0; q < 8; q++) bs += wred[q];
        atomicAdd(&g_sum, bs);
        __threadfence();
        atomicAdd(&g_cnt2, 1u);
        volatile unsigned* vc = &g_cnt2;
        while (*vc < gridDim.x) { }
        __threadfence();
        sBcast = 1.f / *(volatile float*)&g_sum;
    }
    __syncthreads();
    float inv = sBcast;

    int i0 = row0 + t, i1 = row0 + t + THR;
    if (i0 < nrows) out[i0] = e0 * inv;
    if (i1 < nrows) out[i1] = e1 * inv;
}

// ---------------- launcher ----------------
extern "C" void kernel_launch(void* const* d_in, const int* in_sizes, int n_in,
                              void* d_out, int out_size) {
    int o = (n_in >= 20) ? 2 : 0;
    const int*   num_ops = (const int*)d_in[0];
    const float* x       = (const float*)d_in[1 + o];
    const float* y       = (const float*)d_in[2 + o];
    const float* z       = (const float*)d_in[3 + o];
    const float* op_msk  = (const float*)d_in[4 + o];
    const float* pr_msk  = (const float*)d_in[5 + o];
    const float* opW1    = (const float*)d_in[6 + o];
    const float* opb1    = (const float*)d_in[7 + o];
    const float* opW2    = (const float*)d_in[8 + o];
    const float* opb2    = (const float*)d_in[9 + o];
    const float* opW3    = (const float*)d_in[10 + o];
    const float* opb3    = (const float*)d_in[11 + o];
    const float* prW1    = (const float*)d_in[12 + o];
    const float* prb1    = (const float*)d_in[13 + o];
    const float* prW2    = (const float*)d_in[14 + o];
    const float* prb2    = (const float*)d_in[15 + o];
    const float* prW3    = (const float*)d_in[16 + o];
    const float* prb3    = (const float*)d_in[17 + o];
    float* out = (float*)d_out;

    int n = in_sizes[1 + o] / E;   // total ops (102400)

    static int smem_set = 0;
    int dyn = (8192 + ROWS_PB * XPAD) * (int)sizeof(float);   // 73728 B
    if (!smem_set) {
        cudaFuncSetAttribute(k_ops, cudaFuncAttributeMaxDynamicSharedMemorySize, dyn);
        smem_set = 1;
    }

    k_prlvl<<<ND / 8, 512>>>(prW1, prb1, prW2, prb2, prW3, prb3,
                             pr_msk, y, z, out, n);
    k_ops<<<(n + ROWS_PB - 1) / ROWS_PB, THR, dyn>>>(
        x, opW1, opb1, opW2, opb2, opW3, opb3,
        op_msk, num_ops, y, z, out, n);
}

// round 13
// speedup vs baseline: 1.9989x; 1.9989x over previous
#include <cuda_runtime.h>

#define TOTAL_OPS 102400
#define ND 1024
#define NW 64
#define E 256
#define H1N 32
#define H2N 16
#define XPAD 20                      // floats per row in x staging buffer

// ---------------- device scratch (no allocations allowed) ----------------
__device__ float    g_yw_op[ND * H1N];   // y@W1y + b1 + z@W1z (zc folded in)
__device__ unsigned g_maxbits;
__device__ float    g_sum;
__device__ unsigned g_cnt1;
__device__ unsigned g_cnt2;

typedef unsigned long long ull;

// ---------------- packed fp32x2 helpers (sm_103a FFMA2 path) ----------------
__device__ __forceinline__ ull fma2(ull a, ull b, ull c) {
    ull d;
    asm("fma.rn.f32x2 %0, %1, %2, %3;" : "=l"(d) : "l"(a), "l"(b), "l"(c));
    return d;
}
__device__ __forceinline__ ull splat2(float x) {
    ull d;
    asm("mov.b64 %0, {%1, %1};" : "=l"(d) : "f"(x));
    return d;
}
__device__ __forceinline__ void unpack2(ull v, float& lo, float& hi) {
    asm("mov.b64 {%0, %1}, %2;" : "=f"(lo), "=f"(hi) : "l"(v));
}

__device__ __forceinline__ unsigned encf(float f) {
    unsigned b = __float_as_uint(f);
    return (b & 0x80000000u) ? ~b : (b | 0x80000000u);
}
__device__ __forceinline__ float decf(unsigned u) {
    return (u & 0x80000000u) ? __uint_as_float(u & 0x7FFFFFFFu)
                             : __uint_as_float(~u);
}

// ---------------- K1: prlvl branch + produces op yW table -------------------
// 128 blocks x 512 thr, 8 dags/block. Computes:
//   - pr yW for its 8 dags (local use) + zc_pr
//   - op yW for the SAME 8 dags -> g_yw_op (zc_op folded in)
// Block 0 resets k_ops softmax scalars (stream order: before k_ops).
__global__ void __launch_bounds__(512) k_prlvl(
    const float* __restrict__ prW1, const float* __restrict__ prb1,
    const float* __restrict__ prW2, const float* __restrict__ prb2,
    const float* __restrict__ prW3, const float* __restrict__ prb3,
    const float* __restrict__ opW1, const float* __restrict__ opb1,
    const float* __restrict__ msk, const float* __restrict__ y,
    const float* __restrict__ z,
    float* __restrict__ out, int nops)
{
    __shared__ __align__(16) float sW2[H1N * H2N];
    __shared__ float sb2[H2N], sW3[H2N];
    __shared__ float sb3;
    __shared__ float sw1[H1N], szc[H1N], szcop[H1N];
    __shared__ float sbase[8][H1N];
    __shared__ float partP[8][2][H1N];    // pr yW halves
    __shared__ float partO[8][2][H1N];    // op yW halves
    __shared__ float partz[16][H1N];      // [0..7] pr z, [8..15] op z
    __shared__ float redm[8][2], reds[8][2];

    int t = threadIdx.x;
    int g = t >> 6;                      // dag group 0..7
    int w = t & 63;                      // worker 0..63
    int d = blockIdx.x * 8 + g;

    if (blockIdx.x == 0 && t == 0) {
        g_maxbits = 0u; g_sum = 0.f; g_cnt1 = 0u; g_cnt2 = 0u;
    }

    if (t < H1N * H2N) sW2[t] = prW2[t];
    if (t < H2N) { sb2[t] = prb2[t]; sW3[t] = prW3[t]; }
    if (t == 0) sb3 = prb3[0];
    if (t < H1N) sw1[t] = prW1[t];       // limit row of W1

    // --- yW chains: thread = (dd, half, j); 128-k each, for BOTH tables ---
    {
        int dd = t >> 6, half = (t >> 5) & 1, j = t & 31;
        int dg = blockIdx.x * 8 + dd;
        const float* yp = &y[(size_t)dg * E + half * 128];
        const float* Wp = prW1 + (size_t)(1 + half * 128) * H1N + j;
        const float* Wo = opW1 + (size_t)(E + half * 128) * H1N + j;
        float cp = 0.f, co = 0.f;
#pragma unroll 16
        for (int kk = 0; kk < 128; kk++) {
            float yv = yp[kk];
            cp += yv * Wp[kk * H1N];
            co += yv * Wo[kk * H1N];
        }
        partP[dd][half][j] = cp;
        partO[dd][half][j] = co;
    }
    // --- zc chains: threads 0-255 pr, 256-511 op; (q, j) 32-k each ---
    {
        int which = t >> 8;              // 0 = pr, 1 = op
        int q = (t >> 5) & 7, j = t & 31;
        const float* zp = z + q * 32;
        const float* Wp = which
            ? opW1 + (size_t)(2 * E + q * 32) * H1N + j
            : prW1 + (size_t)(E + 1 + q * 32) * H1N + j;
        float c = 0.f;
#pragma unroll 8
        for (int kk = 0; kk < 32; kk++) c += zp[kk] * Wp[kk * H1N];
        partz[which * 8 + q][j] = c;
    }
    __syncthreads();
    if (t < H1N) {                        // combine zc
        float cp = prb1[t], co = opb1[t];
#pragma unroll
        for (int q = 0; q < 8; q++) { cp += partz[q][t]; co += partz[8 + q][t]; }
        szc[t] = cp;
        szcop[t] = co;
    }
    __syncthreads();
    if (t < 8 * H1N) {                    // combine halves; publish op table
        int dd = t >> 5, j = t & 31;
        sbase[dd][j] = partP[dd][0][j] + partP[dd][1][j];
        g_yw_op[(size_t)(blockIdx.x * 8 + dd) * H1N + j] =
            partO[dd][0][j] + partO[dd][1][j] + szcop[j];
    }
    __syncthreads();

    float limit = (float)(w + 1);
    const float* base = sbase[g];
    float h2[H2N];
#pragma unroll
    for (int j2 = 0; j2 < H2N; j2++) h2[j2] = sb2[j2];
#pragma unroll
    for (int j = 0; j < H1N; j++) {
        float v = fmaxf(base[j] + szc[j] + limit * sw1[j], 0.f);
        const float4* w2 = (const float4*)&sW2[j * H2N];
#pragma unroll
        for (int q2 = 0; q2 < 4; q2++) {
            float4 wv = w2[q2];
            h2[4 * q2 + 0] += v * wv.x;
            h2[4 * q2 + 1] += v * wv.y;
            h2[4 * q2 + 2] += v * wv.z;
            h2[4 * q2 + 3] += v * wv.w;
        }
    }
    float logit = sb3;
#pragma unroll
    for (int j2 = 0; j2 < H2N; j2++) logit += fmaxf(h2[j2], 0.f) * sW3[j2];
    logit -= (1.f - msk[d * NW + w]) * 1000.f;

    float m = logit;
#pragma unroll
    for (int o = 16; o > 0; o >>= 1) m = fmaxf(m, __shfl_xor_sync(0xffffffffu, m, o));
    if ((w & 31) == 0) redm[g][w >> 5] = m;
    __syncthreads();
    m = fmaxf(redm[g][0], redm[g][1]);
    float e = expf(logit - m);
    float s = e;
#pragma unroll
    for (int o = 16; o > 0; o >>= 1) s += __shfl_xor_sync(0xffffffffu, s, o);
    if ((w & 31) == 0) reds[g][w >> 5] = s;
    __syncthreads();
    s = reds[g][0] + reds[g][1];
    out[nops + d * NW + w] = e / s;
}

// ---------------- K2: op MLP + fused global softmax (R11-proven) ------------
// 128 thr, 256 rows/block, 400 blocks (3 CTA/SM -> 444 resident >= 400).
// x staged via SMEM (coalesced LDG->STS->LDS.128) in 16-k chunks,
// register-prefetched. Consumption: 4 rows x 16 cols / thread.
__global__ void __launch_bounds__(128, 3) k_ops(
    const float* __restrict__ x, const float* __restrict__ opW1,
    const float* __restrict__ opW2, const float* __restrict__ opb2,
    const float* __restrict__ opW3, const float* __restrict__ opb3,
    const float* __restrict__ op_msk, const int* __restrict__ num_ops,
    float* __restrict__ out, int nrows)
{
    extern __shared__ float dynS[];
    float* sBuf = dynS;                       // 8448 floats (weights / h1)
    float* sX   = dynS + 8448;                // 256*XPAD floats

    __shared__ int sCum[ND];
    __shared__ __align__(16) float sW2[H1N * H2N];
    __shared__ float sb2[H2N], sW3[H2N];
    __shared__ float sb3;
    __shared__ float wred[4];
    __shared__ int wsum[4];
    __shared__ float sBcast;

    int t = threadIdx.x;
    int w = t >> 5, l = t & 31;
    int row0 = blockIdx.x * 256;

    // --- stage W1 x-part [k][32] + small weights ---
    {
        const float4* gW4 = (const float4*)opW1;
        float4* sW4 = (float4*)sBuf;
#pragma unroll
        for (int i = 0; i < 16; i++) sW4[i * 128 + t] = gW4[i * 128 + t];
    }
    for (int i = t; i < H1N * H2N; i += 128) sW2[i] = opW2[i];
    if (t < H2N) { sb2[t] = opb2[t]; sW3[t] = opW3[t]; }
    if (t == 0) sb3 = opb3[0];

    // --- inline inclusive scan of num_ops into sCum ---
    {
        int vloc[8]; int tsum = 0;
#pragma unroll
        for (int i = 0; i < 8; i++) { vloc[i] = num_ops[t * 8 + i]; tsum += vloc[i]; }
        int sc = tsum;
#pragma unroll
        for (int o = 1; o < 32; o <<= 1) {
            int nv = __shfl_up_sync(0xffffffffu, sc, o);
            if (l >= o) sc += nv;
        }
        if (l == 31) wsum[w] = sc;
        __syncthreads();
        int woff = 0;
#pragma unroll
        for (int q = 0; q < 4; q++) if (q < w) woff += wsum[q];
        int run = woff + sc - tsum;
#pragma unroll
        for (int i = 0; i < 8; i++) { run += vloc[i]; sCum[t * 8 + i] = run; }
    }

    // --- main GEMM: 16 chunks of 16 k; coalesced staging ---
    int colhalf = t >> 6;               // 0: cols 0-15, 1: cols 16-31
    int rt = t & 63;

    int sr[8], sc4[8];
#pragma unroll
    for (int i = 0; i < 8; i++) {
        int idx = i * 128 + t;
        sr[i] = idx >> 2;               // row 0..255
        sc4[i] = idx & 3;               // float4 within 16-k chunk
    }

    ull a0[8], a1[8], a2[8], a3[8];
#pragma unroll
    for (int q = 0; q < 8; q++) { a0[q] = 0ull; a1[q] = 0ull; a2[q] = 0ull; a3[q] = 0ull; }
    const ulonglong2* sWu = (const ulonglong2*)sBuf;

    float4 pf[8];
#pragma unroll
    for (int i = 0; i < 8; i++) {
        int row = min(row0 + sr[i], nrows - 1);
        pf[i] = *(const float4*)&x[(size_t)row * E + sc4[i] * 4];
    }

    for (int ch = 0; ch < 16; ch++) {
        __syncthreads();                 // previous chunk fully consumed
#pragma unroll
        for (int i = 0; i < 8; i++)
            *(float4*)&sX[sr[i] * XPAD + sc4[i] * 4] = pf[i];
        if (ch < 15) {
#pragma unroll
            for (int i = 0; i < 8; i++) {
                int row = min(row0 + sr[i], nrows - 1);
                pf[i] = *(const float4*)&x[(size_t)row * E + (ch + 1) * 16 + sc4[i] * 4];
            }
        }
        __syncthreads();                 // chunk ch visible
#pragma unroll
        for (int k4 = 0; k4 < 4; k4++) {
            float4 v0 = *(const float4*)&sX[(rt      ) * XPAD + k4 * 4];
            float4 v1 = *(const float4*)&sX[(rt +  64) * XPAD + k4 * 4];
            float4 v2 = *(const float4*)&sX[(rt + 128) * XPAD + k4 * 4];
            float4 v3 = *(const float4*)&sX[(rt + 192) * XPAD + k4 * 4];
            float f0[4] = {v0.x, v0.y, v0.z, v0.w};
            float f1[4] = {v1.x, v1.y, v1.z, v1.w};
            float f2[4] = {v2.x, v2.y, v2.z, v2.w};
            float f3[4] = {v3.x, v3.y, v3.z, v3.w};
#pragma unroll
            for (int kk = 0; kk < 4; kk++) {
                int k = ch * 16 + k4 * 4 + kk;
                ull s0 = splat2(f0[kk]);
                ull s1 = splat2(f1[kk]);
                ull s2 = splat2(f2[kk]);
                ull s3 = splat2(f3[kk]);
                const ulonglong2* wp = &sWu[k * 8 + colhalf * 4];
                ulonglong2 w0 = wp[0], w1 = wp[1], w2 = wp[2], w3 = wp[3];
                a0[0] = fma2(s0, w0.x, a0[0]); a0[1] = fma2(s0, w0.y, a0[1]);
                a0[2] = fma2(s0, w1.x, a0[2]); a0[3] = fma2(s0, w1.y, a0[3]);
                a0[4] = fma2(s0, w2.x, a0[4]); a0[5] = fma2(s0, w2.y, a0[5]);
                a0[6] = fma2(s0, w3.x, a0[6]); a0[7] = fma2(s0, w3.y, a0[7]);
                a1[0] = fma2(s1, w0.x, a1[0]); a1[1] = fma2(s1, w0.y, a1[1]);
                a1[2] = fma2(s1, w1.x, a1[2]); a1[3] = fma2(s1, w1.y, a1[3]);
                a1[4] = fma2(s1, w2.x, a1[4]); a1[5] = fma2(s1, w2.y, a1[5]);
                a1[6] = fma2(s1, w3.x, a1[6]); a1[7] = fma2(s1, w3.y, a1[7]);
                a2[0] = fma2(s2, w0.x, a2[0]); a2[1] = fma2(s2, w0.y, a2[1]);
                a2[2] = fma2(s2, w1.x, a2[2]); a2[3] = fma2(s2, w1.y, a2[3]);
                a2[4] = fma2(s2, w2.x, a2[4]); a2[5] = fma2(s2, w2.y, a2[5]);
                a2[6] = fma2(s2, w3.x, a2[6]); a2[7] = fma2(s2, w3.y, a2[7]);
                a3[0] = fma2(s3, w0.x, a3[0]); a3[1] = fma2(s3, w0.y, a3[1]);
                a3[2] = fma2(s3, w1.x, a3[2]); a3[3] = fma2(s3, w1.y, a3[3]);
                a3[4] = fma2(s3, w2.x, a3[4]); a3[5] = fma2(s3, w2.y, a3[5]);
                a3[6] = fma2(s3, w3.x, a3[6]); a3[7] = fma2(s3, w3.y, a3[7]);
            }
        }
    }

    // --- stage h1 to sBuf (stride-33), reuse weight region ---
    __syncthreads();
    {
        float* d0 = &sBuf[(rt      ) * 33 + colhalf * 16];
        float* d1 = &sBuf[(rt +  64) * 33 + colhalf * 16];
        float* d2 = &sBuf[(rt + 128) * 33 + colhalf * 16];
        float* d3 = &sBuf[(rt + 192) * 33 + colhalf * 16];
#pragma unroll
        for (int q = 0; q < 8; q++) {
            unpack2(a0[q], d0[2 * q], d0[2 * q + 1]);
            unpack2(a1[q], d1[2 * q], d1[2 * q + 1]);
            unpack2(a2[q], d2[2 * q], d2[2 * q + 1]);
            unpack2(a3[q], d3[2 * q], d3[2 * q + 1]);
        }
    }
    __syncthreads();

    // --- epilogue: 2 rows per thread, logits stay in registers ---
    float lg[2];
    float m = -3.402823466e38f;
#pragma unroll
    for (int r = 0; r < 2; r++) {
        int lr = t + r * 128;
        int i = row0 + lr;
        lg[r] = -3.402823466e38f;
        if (i < nrows) {
            int d = 0;
#pragma unroll
            for (int s = 512; s > 0; s >>= 1)
                if (d + s <= ND - 1 && sCum[d + s - 1] <= i) d += s;
            const float* hs = &sBuf[lr * 33];
            const float* bw = &g_yw_op[d * H1N];     // zc folded in
            float h2[H2N];
#pragma unroll
            for (int j2 = 0; j2 < H2N; j2++) h2[j2] = sb2[j2];
#pragma unroll
            for (int j = 0; j < H1N; j++) {
                float v = fmaxf(hs[j] + bw[j], 0.f);
                const float4* w2 = (const float4*)&sW2[j * H2N];
#pragma unroll
                for (int q2 = 0; q2 < 4; q2++) {
                    float4 wv = w2[q2];
                    h2[4 * q2 + 0] += v * wv.x;
                    h2[4 * q2 + 1] += v * wv.y;
                    h2[4 * q2 + 2] += v * wv.z;
                    h2[4 * q2 + 3] += v * wv.w;
                }
            }
            float logit = sb3;
#pragma unroll
            for (int j2 = 0; j2 < H2N; j2++) logit += fmaxf(h2[j2], 0.f) * sW3[j2];
            logit -= (1.f - op_msk[i]) * 1000.f;
            lg[r] = logit;
            m = fmaxf(m, logit);
        }
    }

#pragma unroll
    for (int o = 16; o > 0; o >>= 1) m = fmaxf(m, __shfl_xor_sync(0xffffffffu, m, o));
    if (l == 0) wred[w] = m;
    __syncthreads();

    // --- grid barrier 1: global max ---
    if (t == 0) {
        float bm = fmaxf(fmaxf(wred[0], wred[1]), fmaxf(wred[2], wred[3]));
        atomicMax(&g_maxbits, encf(bm));
        __threadfence();
        atomicAdd(&g_cnt1, 1u);
        volatile unsigned* vc = &g_cnt1;
        while (*vc < gridDim.x) { }
        __threadfence();
        sBcast = decf(*(volatile unsigned*)&g_maxbits);
    }
    __syncthreads();
    float gm = sBcast;

    float e0 = (lg[0] > -1e38f) ? expf(lg[0] - gm) : 0.f;
    float e1 = (lg[1] > -1e38f) ? expf(lg[1] - gm) : 0.f;
    float s = e0 + e1;
#pragma unroll
    for (int o = 16; o > 0; o >>= 1) s += __shfl_xor_sync(0xffffffffu, s, o);
    if (l == 0) wred[w] = s;
    __syncthreads();

    // --- grid barrier 2: global sum ---
    if (t == 0) {
        float bs = wred[0] + wred[1] + wred[2] + wred[3];
        atomicAdd(&g_sum, bs);
        __threadfence();
        atomicAdd(&g_cnt2, 1u);
        volatile unsigned* vc = &g_cnt2;
        while (*vc < gridDim.x) { }
        __threadfence();
        sBcast = 1.f / *(volatile float*)&g_sum;
    }
    __syncthreads();
    float inv = sBcast;

    int i0 = row0 + t, i1 = row0 + t + 128;
    if (i0 < nrows) out[i0] = e0 * inv;
    if (i1 < nrows) out[i1] = e1 * inv;
}

// ---------------- launcher ----------------
extern "C" void kernel_launch(void* const* d_in, const int* in_sizes, int n_in,
                              void* d_out, int out_size) {
    int o = (n_in >= 20) ? 2 : 0;
    const int*   num_ops = (const int*)d_in[0];
    const float* x       = (const float*)d_in[1 + o];
    const float* y       = (const float*)d_in[2 + o];
    const float* z       = (const float*)d_in[3 + o];
    const float* op_msk  = (const float*)d_in[4 + o];
    const float* pr_msk  = (const float*)d_in[5 + o];
    const float* opW1    = (const float*)d_in[6 + o];
    const float* opb1    = (const float*)d_in[7 + o];
    const float* opW2    = (const float*)d_in[8 + o];
    const float* opb2    = (const float*)d_in[9 + o];
    const float* opW3    = (const float*)d_in[10 + o];
    const float* opb3    = (const float*)d_in[11 + o];
    const float* prW1    = (const float*)d_in[12 + o];
    const float* prb1    = (const float*)d_in[13 + o];
    const float* prW2    = (const float*)d_in[14 + o];
    const float* prb2    = (const float*)d_in[15 + o];
    const float* prW3    = (const float*)d_in[16 + o];
    const float* prb3    = (const float*)d_in[17 + o];
    float* out = (float*)d_out;

    int n = in_sizes[1 + o] / E;   // total ops (102400)

    static int smem_set = 0;
    int dyn = (8448 + 256 * XPAD) * (int)sizeof(float);   // 54272 B
    if (!smem_set) {
        cudaFuncSetAttribute(k_ops, cudaFuncAttributeMaxDynamicSharedMemorySize, dyn);
        smem_set = 1;
    }

    k_prlvl<<<ND / 8, 512>>>(prW1, prb1, prW2, prb2, prW3, prb3,
                             opW1, opb1, pr_msk, y, z, out, n);
    k_ops<<<(n + 255) / 256, 128, dyn>>>(x, opW1, opW2, opb2, opW3, opb3,
                                         op_msk, num_ops, out, n);
}